// round 2
// baseline (speedup 1.0000x reference)
#include <cuda_runtime.h>

#define DIMK 1024
#define BSZ  2
#define SEQ  4096
#define H    16
#define HD   64
#define M_TOT (BSZ * SEQ)   // 8192

// Scratch (allocation-free): Q/K/V in [B,H,S,hd], attention out in [B,S,D]
__device__ float g_q[(size_t)BSZ * H * SEQ * HD];
__device__ float g_k[(size_t)BSZ * H * SEQ * HD];
__device__ float g_v[(size_t)BSZ * H * SEQ * HD];
__device__ float g_att[(size_t)BSZ * SEQ * DIMK];

// ---------------------------------------------------------------------------
// C = A @ Bw^T + bias.  A: [M, 1024] row-major, Bw: [N(out), 1024(in)] row-major.
// layout 0: C row-major [M, 1024] ; layout 1: scatter to [B,H,S,hd]
// 64x64 tile, BK=16, 256 threads, 4x4 microtile.
// ---------------------------------------------------------------------------
__global__ void __launch_bounds__(256) gemm_bias(const float* __restrict__ A,
                                                 const float* __restrict__ Bw,
                                                 const float* __restrict__ bias,
                                                 float* __restrict__ C,
                                                 int layout)
{
    __shared__ __align__(16) float As[16][68];
    __shared__ __align__(16) float Bs[16][68];

    const int tid = threadIdx.x;
    const int tm = tid >> 4;          // 0..15
    const int tn = tid & 15;          // 0..15
    const int m0 = blockIdx.y << 6;
    const int n0 = blockIdx.x << 6;
    const int lrow = tid >> 2;        // 0..63
    const int lq   = (tid & 3) << 2;  // 0,4,8,12

    const float* Aptr = A  + (size_t)(m0 + lrow) * DIMK + lq;
    const float* Bptr = Bw + (size_t)(n0 + lrow) * DIMK + lq;

    float acc[4][4] = {};

    for (int k0 = 0; k0 < DIMK; k0 += 16) {
        float4 a = *(const float4*)(Aptr + k0);
        float4 b = *(const float4*)(Bptr + k0);
        __syncthreads();
        As[lq + 0][lrow] = a.x; As[lq + 1][lrow] = a.y;
        As[lq + 2][lrow] = a.z; As[lq + 3][lrow] = a.w;
        Bs[lq + 0][lrow] = b.x; Bs[lq + 1][lrow] = b.y;
        Bs[lq + 2][lrow] = b.z; Bs[lq + 3][lrow] = b.w;
        __syncthreads();
#pragma unroll
        for (int k = 0; k < 16; k++) {
            float4 av = *(const float4*)&As[k][tm << 2];
            float4 bv = *(const float4*)&Bs[k][tn << 2];
            acc[0][0] += av.x * bv.x; acc[0][1] += av.x * bv.y;
            acc[0][2] += av.x * bv.z; acc[0][3] += av.x * bv.w;
            acc[1][0] += av.y * bv.x; acc[1][1] += av.y * bv.y;
            acc[1][2] += av.y * bv.z; acc[1][3] += av.y * bv.w;
            acc[2][0] += av.z * bv.x; acc[2][1] += av.z * bv.y;
            acc[2][2] += av.z * bv.z; acc[2][3] += av.z * bv.w;
            acc[3][0] += av.w * bv.x; acc[3][1] += av.w * bv.y;
            acc[3][2] += av.w * bv.z; acc[3][3] += av.w * bv.w;
        }
    }

#pragma unroll
    for (int i = 0; i < 4; i++) {
        const int m = m0 + (tm << 2) + i;
#pragma unroll
        for (int j = 0; j < 4; j++) {
            const int n = n0 + (tn << 2) + j;
            const float v = acc[i][j] + bias[n];
            if (layout == 0) {
                C[(size_t)m * DIMK + n] = v;
            } else {
                const int b_ = m >> 12, s_ = m & 4095;
                const int h_ = n >> 6,  d_ = n & 63;
                C[(((size_t)(b_ * H + h_)) * SEQ + s_) * HD + d_] = v;
            }
        }
    }
}

// ---------------------------------------------------------------------------
// Sliding-window attention: one block per (b, h, 64-query tile).
// Keys for query tile [p0, p0+63]: [p0-512, p0+63], mask  p-511 <= t <= p.
// Flash-style online softmax; Ps aliases Ks.
// ---------------------------------------------------------------------------
#define SROW 68
#define SMEM_ATTN (3 * 64 * SROW * 4)

__global__ void __launch_bounds__(256) attn_kernel()
{
    extern __shared__ __align__(16) float sm[];
    float* Qs = sm;                 // [64][68]  Qs[d][q]  (d-major)
    float* Ks = sm + 64 * SROW;     // [64][68]  Ks[d][t] ; later reused as Ps[t][q]
    float* Vs = sm + 2 * 64 * SROW; // [64][68]  Vs[t][d]

    const int tid = threadIdx.x;
    const int tm = tid >> 4;
    const int tn = tid & 15;
    const int qt = blockIdx.x & 63;
    const int h  = (blockIdx.x >> 6) & 15;
    const int b  = blockIdx.x >> 10;
    const int p0 = qt << 6;

    const size_t headoff = ((size_t)(b * H + h)) * SEQ * HD;
    const float* qbase = g_q + headoff;
    const float* kbase = g_k + headoff;
    const float* vbase = g_v + headoff;

    // Load Q tile transposed: Qs[d][q]
#pragma unroll
    for (int it = 0; it < 4; it++) {
        const int idx  = tid + (it << 8);
        const int row  = idx >> 4;
        const int quad = (idx & 15) << 2;
        float4 v = *(const float4*)(qbase + (size_t)(p0 + row) * HD + quad);
        Qs[(quad + 0) * SROW + row] = v.x;
        Qs[(quad + 1) * SROW + row] = v.y;
        Qs[(quad + 2) * SROW + row] = v.z;
        Qs[(quad + 3) * SROW + row] = v.w;
    }

    float m_i[4], l_i[4], o[4][4];
#pragma unroll
    for (int i = 0; i < 4; i++) {
        m_i[i] = -1e30f; l_i[i] = 0.f;
#pragma unroll
        for (int j = 0; j < 4; j++) o[i][j] = 0.f;
    }

    const int kt0 = (qt >= 8) ? (qt - 8) : 0;
    for (int kt = kt0; kt <= qt; kt++) {
        const int t0 = kt << 6;

        // Stage K/V tile in registers (overlaps prior PV compute)
        float4 kr[4], vr[4];
#pragma unroll
        for (int it = 0; it < 4; it++) {
            const int idx  = tid + (it << 8);
            const int row  = idx >> 4;
            const int quad = (idx & 15) << 2;
            kr[it] = *(const float4*)(kbase + (size_t)(t0 + row) * HD + quad);
            vr[it] = *(const float4*)(vbase + (size_t)(t0 + row) * HD + quad);
        }
        __syncthreads();   // previous iteration's Ps/Vs reads done
#pragma unroll
        for (int it = 0; it < 4; it++) {
            const int idx  = tid + (it << 8);
            const int row  = idx >> 4;
            const int quad = (idx & 15) << 2;
            Ks[(quad + 0) * SROW + row] = kr[it].x;
            Ks[(quad + 1) * SROW + row] = kr[it].y;
            Ks[(quad + 2) * SROW + row] = kr[it].z;
            Ks[(quad + 3) * SROW + row] = kr[it].w;
            *(float4*)&Vs[row * SROW + quad] = vr[it];
        }
        __syncthreads();

        // S = Q K^T  (4x4 microtile)
        float s4[4][4] = {};
#pragma unroll
        for (int d = 0; d < 64; d++) {
            float4 qv = *(const float4*)&Qs[d * SROW + (tm << 2)];
            float4 kv = *(const float4*)&Ks[d * SROW + (tn << 2)];
            s4[0][0] += qv.x * kv.x; s4[0][1] += qv.x * kv.y;
            s4[0][2] += qv.x * kv.z; s4[0][3] += qv.x * kv.w;
            s4[1][0] += qv.y * kv.x; s4[1][1] += qv.y * kv.y;
            s4[1][2] += qv.y * kv.z; s4[1][3] += qv.y * kv.w;
            s4[2][0] += qv.z * kv.x; s4[2][1] += qv.z * kv.y;
            s4[2][2] += qv.z * kv.z; s4[2][3] += qv.z * kv.w;
            s4[3][0] += qv.w * kv.x; s4[3][1] += qv.w * kv.y;
            s4[3][2] += qv.w * kv.z; s4[3][3] += qv.w * kv.w;
        }

        // scale + mask + online softmax (rows replicated over the 16 tn-threads;
        // lane group = 16 consecutive lanes -> xor 8,4,2,1 reductions)
#pragma unroll
        for (int i = 0; i < 4; i++) {
            const int q = p0 + (tm << 2) + i;
            float rmax = -1e30f;
#pragma unroll
            for (int j = 0; j < 4; j++) {
                const int t = t0 + (tn << 2) + j;
                float sc = s4[i][j] * 0.125f;               // hd^-0.5
                if (t > q || t + 511 < q) sc = -1e30f;      // window mask
                s4[i][j] = sc;
                rmax = fmaxf(rmax, sc);
            }
            rmax = fmaxf(rmax, __shfl_xor_sync(0xffffffffu, rmax, 8));
            rmax = fmaxf(rmax, __shfl_xor_sync(0xffffffffu, rmax, 4));
            rmax = fmaxf(rmax, __shfl_xor_sync(0xffffffffu, rmax, 2));
            rmax = fmaxf(rmax, __shfl_xor_sync(0xffffffffu, rmax, 1));

            const float mn    = fmaxf(m_i[i], rmax);
            const float alpha = __expf(m_i[i] - mn);
            m_i[i] = mn;

            float rs = 0.f;
#pragma unroll
            for (int j = 0; j < 4; j++) {
                // guard: fully-masked tile row must give p = 0, not exp(0)
                const float e = (s4[i][j] < -1e29f) ? 0.f : __expf(s4[i][j] - mn);
                s4[i][j] = e;
                rs += e;
            }
            rs += __shfl_xor_sync(0xffffffffu, rs, 8);
            rs += __shfl_xor_sync(0xffffffffu, rs, 4);
            rs += __shfl_xor_sync(0xffffffffu, rs, 2);
            rs += __shfl_xor_sync(0xffffffffu, rs, 1);

            l_i[i] = l_i[i] * alpha + rs;
#pragma unroll
            for (int j = 0; j < 4; j++) o[i][j] *= alpha;
        }

        __syncthreads();   // all threads finished reading Ks before P overwrite
        float* Ps = Ks;    // Ps[t][q]
#pragma unroll
        for (int j = 0; j < 4; j++)
#pragma unroll
            for (int i = 0; i < 4; i++)
                Ps[((tn << 2) + j) * SROW + (tm << 2) + i] = s4[i][j];
        __syncthreads();

        // O += P @ V
#pragma unroll
        for (int t = 0; t < 64; t++) {
            float4 pv = *(const float4*)&Ps[t * SROW + (tm << 2)];
            float4 vv = *(const float4*)&Vs[t * SROW + (tn << 2)];
            o[0][0] += pv.x * vv.x; o[0][1] += pv.x * vv.y;
            o[0][2] += pv.x * vv.z; o[0][3] += pv.x * vv.w;
            o[1][0] += pv.y * vv.x; o[1][1] += pv.y * vv.y;
            o[1][2] += pv.y * vv.z; o[1][3] += pv.y * vv.w;
            o[2][0] += pv.z * vv.x; o[2][1] += pv.z * vv.y;
            o[2][2] += pv.z * vv.z; o[2][3] += pv.z * vv.w;
            o[3][0] += pv.w * vv.x; o[3][1] += pv.w * vv.y;
            o[3][2] += pv.w * vv.z; o[3][3] += pv.w * vv.w;
        }
    }

    // epilogue: normalize, scatter to [B,S,D]
#pragma unroll
    for (int i = 0; i < 4; i++) {
        const float inv = 1.0f / l_i[i];
        const int srow = p0 + (tm << 2) + i;
        float4 r;
        r.x = o[i][0] * inv; r.y = o[i][1] * inv;
        r.z = o[i][2] * inv; r.w = o[i][3] * inv;
        *(float4*)&g_att[((size_t)b * SEQ + srow) * DIMK + h * HD + (tn << 2)] = r;
    }
}

// ---------------------------------------------------------------------------
extern "C" void kernel_launch(void* const* d_in, const int* in_sizes, int n_in,
                              void* d_out, int out_size)
{
    const float* x  = (const float*)d_in[0];
    const float* Wq = (const float*)d_in[1];
    const float* bq = (const float*)d_in[2];
    const float* Wk = (const float*)d_in[3];
    const float* bk = (const float*)d_in[4];
    const float* Wv = (const float*)d_in[5];
    const float* bv = (const float*)d_in[6];
    const float* Wo = (const float*)d_in[7];
    const float* bo = (const float*)d_in[8];
    float* out = (float*)d_out;

    float *qp, *kp, *vp, *ap;
    cudaGetSymbolAddress((void**)&qp, g_q);
    cudaGetSymbolAddress((void**)&kp, g_k);
    cudaGetSymbolAddress((void**)&vp, g_v);
    cudaGetSymbolAddress((void**)&ap, g_att);

    cudaFuncSetAttribute(attn_kernel,
                         cudaFuncAttributeMaxDynamicSharedMemorySize, SMEM_ATTN);

    dim3 gg(DIMK / 64, M_TOT / 64);   // (16, 128)
    gemm_bias<<<gg, 256>>>(x, Wq, bq, qp, 1);
    gemm_bias<<<gg, 256>>>(x, Wk, bk, kp, 1);
    gemm_bias<<<gg, 256>>>(x, Wv, bv, vp, 1);
    attn_kernel<<<BSZ * H * (SEQ / 64), 256, SMEM_ATTN>>>();  // 2048 blocks
    gemm_bias<<<gg, 256>>>(ap, Wo, bo, out, 0);
}

// round 6
// speedup vs baseline: 2.2872x; 2.2872x over previous
#include <cuda_runtime.h>
#include <cstdint>

#define DIMK 1024
#define BSZ  2
#define SEQ  4096
#define H    16
#define HD   64
#define M_TOT (BSZ * SEQ)   // 8192

// ---------------------------------------------------------------------------
// Scratch (allocation-free)
// ---------------------------------------------------------------------------
__device__ float g_q[(size_t)BSZ * H * SEQ * HD];
__device__ float g_k[(size_t)BSZ * H * SEQ * HD];
__device__ float g_v[(size_t)BSZ * H * SEQ * HD];
__device__ float g_att[(size_t)BSZ * SEQ * DIMK];

__device__ __forceinline__ uint32_t f32_tf32(float f) {
    uint32_t r; asm("cvt.rna.tf32.f32 %0, %1;" : "=r"(r) : "f"(f)); return r;
}

__device__ __forceinline__ void mma_tf32(float& c0, float& c1, float& c2, float& c3,
                                         uint32_t a0, uint32_t a1, uint32_t a2, uint32_t a3,
                                         uint32_t b0, uint32_t b1) {
    asm volatile("mma.sync.aligned.m16n8k8.row.col.f32.tf32.tf32.f32 "
        "{%0,%1,%2,%3}, {%4,%5,%6,%7}, {%8,%9}, {%0,%1,%2,%3};"
        : "+f"(c0), "+f"(c1), "+f"(c2), "+f"(c3)
        : "r"(a0), "r"(a1), "r"(a2), "r"(a3), "r"(b0), "r"(b1));
}

// ---------------------------------------------------------------------------
// tf32 mma.sync GEMM: C[M,1024] = A[M,1024] @ W[N,K]^T + bias
// CTA 128x128, BK=32, 256 thr, 8 warps (2M x 4N), warp tile 64x32.
// layout 0: row-major [M,1024] ; layout 1: scatter to [B,H,S,hd]
// ---------------------------------------------------------------------------
#define BM 128
#define BN 128
#define BK 32
#define KSTRIDE 36   // 32 + 4 pad (16B-aligned rows, conflict-free frag loads)

__global__ void __launch_bounds__(256) gemm_mma(const float* __restrict__ A,
                                                const float* __restrict__ W,
                                                const float* __restrict__ bias,
                                                float* __restrict__ C,
                                                int layout)
{
    __shared__ __align__(16) uint32_t As[BM][KSTRIDE];
    __shared__ __align__(16) uint32_t Bs[BN][KSTRIDE];

    const int tid  = threadIdx.x;
    const int wid  = tid >> 5;
    const int lane = tid & 31;
    const int g    = lane >> 2;       // group 0..7
    const int t    = lane & 3;        // thread-in-group
    const int wm   = wid & 1;         // 2 M-warps
    const int wn   = wid >> 1;        // 4 N-warps
    const int m0   = blockIdx.y * BM;
    const int n0   = blockIdx.x * BN;

    const int lrow = tid >> 3;        // 0..31
    const int lc4  = (tid & 7) << 2;  // 0..28 step 4

    float acc[4][4][4];
#pragma unroll
    for (int i = 0; i < 4; i++)
#pragma unroll
        for (int j = 0; j < 4; j++)
#pragma unroll
            for (int r = 0; r < 4; r++) acc[i][j][r] = 0.f;

    const int warpAm = wm * 64;   // warp M offset in tile
    const int warpBn = wn * 32;   // warp N offset in tile

    for (int k0 = 0; k0 < DIMK; k0 += BK) {
        // stage A/W chunk in registers (overlaps previous compute)
        float4 av[4], wv[4];
#pragma unroll
        for (int it = 0; it < 4; it++) {
            const int row = lrow + (it << 5);
            av[it] = *(const float4*)(A + (size_t)(m0 + row) * DIMK + k0 + lc4);
            wv[it] = *(const float4*)(W + (size_t)(n0 + row) * DIMK + k0 + lc4);
        }
        __syncthreads();
#pragma unroll
        for (int it = 0; it < 4; it++) {
            const int row = lrow + (it << 5);
            uint4 ta, tw;
            ta.x = f32_tf32(av[it].x); ta.y = f32_tf32(av[it].y);
            ta.z = f32_tf32(av[it].z); ta.w = f32_tf32(av[it].w);
            tw.x = f32_tf32(wv[it].x); tw.y = f32_tf32(wv[it].y);
            tw.z = f32_tf32(wv[it].z); tw.w = f32_tf32(wv[it].w);
            *(uint4*)&As[row][lc4] = ta;
            *(uint4*)&Bs[row][lc4] = tw;
        }
        __syncthreads();

#pragma unroll
        for (int ks = 0; ks < 4; ks++) {
            const int kk = ks << 3;
            uint32_t af[4][4], bf[4][2];
#pragma unroll
            for (int mt = 0; mt < 4; mt++) {
                const int rb = warpAm + (mt << 4);
                af[mt][0] = As[rb + g    ][kk + t    ];
                af[mt][1] = As[rb + g + 8][kk + t    ];
                af[mt][2] = As[rb + g    ][kk + t + 4];
                af[mt][3] = As[rb + g + 8][kk + t + 4];
            }
#pragma unroll
            for (int nt = 0; nt < 4; nt++) {
                const int nb = warpBn + (nt << 3);
                bf[nt][0] = Bs[nb + g][kk + t    ];
                bf[nt][1] = Bs[nb + g][kk + t + 4];
            }
#pragma unroll
            for (int mt = 0; mt < 4; mt++)
#pragma unroll
                for (int nt = 0; nt < 4; nt++)
                    mma_tf32(acc[mt][nt][0], acc[mt][nt][1],
                             acc[mt][nt][2], acc[mt][nt][3],
                             af[mt][0], af[mt][1], af[mt][2], af[mt][3],
                             bf[nt][0], bf[nt][1]);
        }
    }

    // epilogue: c0/c1 -> (row g, cols 2t,2t+1); c2/c3 -> (row g+8)
#pragma unroll
    for (int nt = 0; nt < 4; nt++) {
        const int n = n0 + warpBn + (nt << 3) + (t << 1);
        const float bx = bias[n], by = bias[n + 1];
#pragma unroll
        for (int mt = 0; mt < 4; mt++) {
            const int r0 = m0 + warpAm + (mt << 4) + g;
            const int r1 = r0 + 8;
            float2 v0 = make_float2(acc[mt][nt][0] + bx, acc[mt][nt][1] + by);
            float2 v1 = make_float2(acc[mt][nt][2] + bx, acc[mt][nt][3] + by);
            if (layout == 0) {
                *(float2*)(C + (size_t)r0 * DIMK + n) = v0;
                *(float2*)(C + (size_t)r1 * DIMK + n) = v1;
            } else {
                const int h_ = n >> 6, d_ = n & 63;
                const int b0_ = r0 >> 12, s0_ = r0 & 4095;
                const int b1_ = r1 >> 12, s1_ = r1 & 4095;
                *(float2*)(C + (((size_t)(b0_ * H + h_)) * SEQ + s0_) * HD + d_) = v0;
                *(float2*)(C + (((size_t)(b1_ * H + h_)) * SEQ + s1_) * HD + d_) = v1;
            }
        }
    }
}

// ---------------------------------------------------------------------------
// Sliding-window attention (unchanged, known good): block per (b,h,64-q tile)
// ---------------------------------------------------------------------------
#define SROW 68
#define SMEM_ATTN (3 * 64 * SROW * 4)

__global__ void __launch_bounds__(256) attn_kernel()
{
    extern __shared__ __align__(16) float smf[];
    float* Qs = smf;
    float* Ks = smf + 64 * SROW;
    float* Vs = smf + 2 * 64 * SROW;

    const int tid = threadIdx.x;
    const int tm = tid >> 4;
    const int tn = tid & 15;
    const int qt = blockIdx.x & 63;
    const int h  = (blockIdx.x >> 6) & 15;
    const int b  = blockIdx.x >> 10;
    const int p0 = qt << 6;

    const size_t headoff = ((size_t)(b * H + h)) * SEQ * HD;
    const float* qbase = g_q + headoff;
    const float* kbase = g_k + headoff;
    const float* vbase = g_v + headoff;

#pragma unroll
    for (int it = 0; it < 4; it++) {
        const int idx  = tid + (it << 8);
        const int row  = idx >> 4;
        const int quad = (idx & 15) << 2;
        float4 v = *(const float4*)(qbase + (size_t)(p0 + row) * HD + quad);
        Qs[(quad + 0) * SROW + row] = v.x;
        Qs[(quad + 1) * SROW + row] = v.y;
        Qs[(quad + 2) * SROW + row] = v.z;
        Qs[(quad + 3) * SROW + row] = v.w;
    }

    float m_i[4], l_i[4], o[4][4];
#pragma unroll
    for (int i = 0; i < 4; i++) {
        m_i[i] = -1e30f; l_i[i] = 0.f;
#pragma unroll
        for (int j = 0; j < 4; j++) o[i][j] = 0.f;
    }

    const int kt0 = (qt >= 8) ? (qt - 8) : 0;
    for (int kt = kt0; kt <= qt; kt++) {
        const int t0 = kt << 6;

        float4 kr[4], vr[4];
#pragma unroll
        for (int it = 0; it < 4; it++) {
            const int idx  = tid + (it << 8);
            const int row  = idx >> 4;
            const int quad = (idx & 15) << 2;
            kr[it] = *(const float4*)(kbase + (size_t)(t0 + row) * HD + quad);
            vr[it] = *(const float4*)(vbase + (size_t)(t0 + row) * HD + quad);
        }
        __syncthreads();
#pragma unroll
        for (int it = 0; it < 4; it++) {
            const int idx  = tid + (it << 8);
            const int row  = idx >> 4;
            const int quad = (idx & 15) << 2;
            Ks[(quad + 0) * SROW + row] = kr[it].x;
            Ks[(quad + 1) * SROW + row] = kr[it].y;
            Ks[(quad + 2) * SROW + row] = kr[it].z;
            Ks[(quad + 3) * SROW + row] = kr[it].w;
            *(float4*)&Vs[row * SROW + quad] = vr[it];
        }
        __syncthreads();

        float s4[4][4] = {};
#pragma unroll
        for (int d = 0; d < 64; d++) {
            float4 qv = *(const float4*)&Qs[d * SROW + (tm << 2)];
            float4 kv = *(const float4*)&Ks[d * SROW + (tn << 2)];
            s4[0][0] += qv.x * kv.x; s4[0][1] += qv.x * kv.y;
            s4[0][2] += qv.x * kv.z; s4[0][3] += qv.x * kv.w;
            s4[1][0] += qv.y * kv.x; s4[1][1] += qv.y * kv.y;
            s4[1][2] += qv.y * kv.z; s4[1][3] += qv.y * kv.w;
            s4[2][0] += qv.z * kv.x; s4[2][1] += qv.z * kv.y;
            s4[2][2] += qv.z * kv.z; s4[2][3] += qv.z * kv.w;
            s4[3][0] += qv.w * kv.x; s4[3][1] += qv.w * kv.y;
            s4[3][2] += qv.w * kv.z; s4[3][3] += qv.w * kv.w;
        }

#pragma unroll
        for (int i = 0; i < 4; i++) {
            const int q = p0 + (tm << 2) + i;
            float rmax = -1e30f;
#pragma unroll
            for (int j = 0; j < 4; j++) {
                const int t = t0 + (tn << 2) + j;
                float sc = s4[i][j] * 0.125f;
                if (t > q || t + 511 < q) sc = -1e30f;
                s4[i][j] = sc;
                rmax = fmaxf(rmax, sc);
            }
            rmax = fmaxf(rmax, __shfl_xor_sync(0xffffffffu, rmax, 8));
            rmax = fmaxf(rmax, __shfl_xor_sync(0xffffffffu, rmax, 4));
            rmax = fmaxf(rmax, __shfl_xor_sync(0xffffffffu, rmax, 2));
            rmax = fmaxf(rmax, __shfl_xor_sync(0xffffffffu, rmax, 1));

            const float mn    = fmaxf(m_i[i], rmax);
            const float alpha = __expf(m_i[i] - mn);
            m_i[i] = mn;

            float rs = 0.f;
#pragma unroll
            for (int j = 0; j < 4; j++) {
                const float e = (s4[i][j] < -1e29f) ? 0.f : __expf(s4[i][j] - mn);
                s4[i][j] = e;
                rs += e;
            }
            rs += __shfl_xor_sync(0xffffffffu, rs, 8);
            rs += __shfl_xor_sync(0xffffffffu, rs, 4);
            rs += __shfl_xor_sync(0xffffffffu, rs, 2);
            rs += __shfl_xor_sync(0xffffffffu, rs, 1);

            l_i[i] = l_i[i] * alpha + rs;
#pragma unroll
            for (int j = 0; j < 4; j++) o[i][j] *= alpha;
        }

        __syncthreads();
        float* Ps = Ks;
#pragma unroll
        for (int j = 0; j < 4; j++)
#pragma unroll
            for (int i = 0; i < 4; i++)
                Ps[((tn << 2) + j) * SROW + (tm << 2) + i] = s4[i][j];
        __syncthreads();

#pragma unroll
        for (int t = 0; t < 64; t++) {
            float4 pv = *(const float4*)&Ps[t * SROW + (tm << 2)];
            float4 vv = *(const float4*)&Vs[t * SROW + (tn << 2)];
            o[0][0] += pv.x * vv.x; o[0][1] += pv.x * vv.y;
            o[0][2] += pv.x * vv.z; o[0][3] += pv.x * vv.w;
            o[1][0] += pv.y * vv.x; o[1][1] += pv.y * vv.y;
            o[1][2] += pv.y * vv.z; o[1][3] += pv.y * vv.w;
            o[2][0] += pv.z * vv.x; o[2][1] += pv.z * vv.y;
            o[2][2] += pv.z * vv.z; o[2][3] += pv.z * vv.w;
            o[3][0] += pv.w * vv.x; o[3][1] += pv.w * vv.y;
            o[3][2] += pv.w * vv.z; o[3][3] += pv.w * vv.w;
        }
    }

#pragma unroll
    for (int i = 0; i < 4; i++) {
        const float inv = 1.0f / l_i[i];
        const int srow = p0 + (tm << 2) + i;
        float4 r;
        r.x = o[i][0] * inv; r.y = o[i][1] * inv;
        r.z = o[i][2] * inv; r.w = o[i][3] * inv;
        *(float4*)&g_att[((size_t)b * SEQ + srow) * DIMK + h * HD + (tn << 2)] = r;
    }
}

// ---------------------------------------------------------------------------
extern "C" void kernel_launch(void* const* d_in, const int* in_sizes, int n_in,
                              void* d_out, int out_size)
{
    const float* x  = (const float*)d_in[0];
    const float* Wq = (const float*)d_in[1];
    const float* bq = (const float*)d_in[2];
    const float* Wk = (const float*)d_in[3];
    const float* bk = (const float*)d_in[4];
    const float* Wv = (const float*)d_in[5];
    const float* bv = (const float*)d_in[6];
    const float* Wo = (const float*)d_in[7];
    const float* bo = (const float*)d_in[8];
    float* out = (float*)d_out;

    float *qp, *kp, *vp, *ap;
    cudaGetSymbolAddress((void**)&qp, g_q);
    cudaGetSymbolAddress((void**)&kp, g_k);
    cudaGetSymbolAddress((void**)&vp, g_v);
    cudaGetSymbolAddress((void**)&ap, g_att);

    cudaFuncSetAttribute(attn_kernel,
                         cudaFuncAttributeMaxDynamicSharedMemorySize, SMEM_ATTN);

    dim3 gg(DIMK / BN, M_TOT / BM);   // (8, 64) = 512 CTAs
    gemm_mma<<<gg, 256>>>(x, Wq, bq, qp, 1);
    gemm_mma<<<gg, 256>>>(x, Wk, bk, kp, 1);
    gemm_mma<<<gg, 256>>>(x, Wv, bv, vp, 1);
    attn_kernel<<<BSZ * H * (SEQ / 64), 256, SMEM_ATTN>>>();
    gemm_mma<<<gg, 256>>>(ap, Wo, bo, out, 0);
}

// round 7
// speedup vs baseline: 3.3315x; 1.4566x over previous
#include <cuda_runtime.h>
#include <cstdint>

#define DIMK 1024
#define BSZ  2
#define SEQ  4096
#define H    16
#define HD   64
#define M_TOT (BSZ * SEQ)   // 8192

// ---------------------------------------------------------------------------
// Scratch (allocation-free)
// ---------------------------------------------------------------------------
__device__ float g_q[(size_t)BSZ * H * SEQ * HD];
__device__ float g_k[(size_t)BSZ * H * SEQ * HD];
__device__ float g_v[(size_t)BSZ * H * SEQ * HD];
__device__ float g_att[(size_t)BSZ * SEQ * DIMK];

__device__ __forceinline__ uint32_t f32_tf32(float f) {
    uint32_t r; asm("cvt.rna.tf32.f32 %0, %1;" : "=r"(r) : "f"(f)); return r;
}
__device__ __forceinline__ float ex2f(float x) {
    float r; asm("ex2.approx.f32 %0, %1;" : "=f"(r) : "f"(x)); return r;
}

__device__ __forceinline__ void mma_tf32(float& c0, float& c1, float& c2, float& c3,
                                         uint32_t a0, uint32_t a1, uint32_t a2, uint32_t a3,
                                         uint32_t b0, uint32_t b1) {
    asm volatile("mma.sync.aligned.m16n8k8.row.col.f32.tf32.tf32.f32 "
        "{%0,%1,%2,%3}, {%4,%5,%6,%7}, {%8,%9}, {%0,%1,%2,%3};"
        : "+f"(c0), "+f"(c1), "+f"(c2), "+f"(c3)
        : "r"(a0), "r"(a1), "r"(a2), "r"(a3), "r"(b0), "r"(b1));
}

// ---------------------------------------------------------------------------
// tf32 mma.sync GEMM (unchanged, known good)
// ---------------------------------------------------------------------------
#define BM 128
#define BN 128
#define BK 32
#define KSTRIDE 36

__global__ void __launch_bounds__(256) gemm_mma(const float* __restrict__ A,
                                                const float* __restrict__ W,
                                                const float* __restrict__ bias,
                                                float* __restrict__ C,
                                                int layout)
{
    __shared__ __align__(16) uint32_t As[BM][KSTRIDE];
    __shared__ __align__(16) uint32_t Bs[BN][KSTRIDE];

    const int tid  = threadIdx.x;
    const int wid  = tid >> 5;
    const int lane = tid & 31;
    const int g    = lane >> 2;
    const int t    = lane & 3;
    const int wm   = wid & 1;
    const int wn   = wid >> 1;
    const int m0   = blockIdx.y * BM;
    const int n0   = blockIdx.x * BN;

    const int lrow = tid >> 3;
    const int lc4  = (tid & 7) << 2;

    float acc[4][4][4];
#pragma unroll
    for (int i = 0; i < 4; i++)
#pragma unroll
        for (int j = 0; j < 4; j++)
#pragma unroll
            for (int r = 0; r < 4; r++) acc[i][j][r] = 0.f;

    const int warpAm = wm * 64;
    const int warpBn = wn * 32;

    for (int k0 = 0; k0 < DIMK; k0 += BK) {
        float4 av[4], wv[4];
#pragma unroll
        for (int it = 0; it < 4; it++) {
            const int row = lrow + (it << 5);
            av[it] = *(const float4*)(A + (size_t)(m0 + row) * DIMK + k0 + lc4);
            wv[it] = *(const float4*)(W + (size_t)(n0 + row) * DIMK + k0 + lc4);
        }
        __syncthreads();
#pragma unroll
        for (int it = 0; it < 4; it++) {
            const int row = lrow + (it << 5);
            uint4 ta, tw;
            ta.x = f32_tf32(av[it].x); ta.y = f32_tf32(av[it].y);
            ta.z = f32_tf32(av[it].z); ta.w = f32_tf32(av[it].w);
            tw.x = f32_tf32(wv[it].x); tw.y = f32_tf32(wv[it].y);
            tw.z = f32_tf32(wv[it].z); tw.w = f32_tf32(wv[it].w);
            *(uint4*)&As[row][lc4] = ta;
            *(uint4*)&Bs[row][lc4] = tw;
        }
        __syncthreads();

#pragma unroll
        for (int ks = 0; ks < 4; ks++) {
            const int kk = ks << 3;
            uint32_t af[4][4], bf[4][2];
#pragma unroll
            for (int mt = 0; mt < 4; mt++) {
                const int rb = warpAm + (mt << 4);
                af[mt][0] = As[rb + g    ][kk + t    ];
                af[mt][1] = As[rb + g + 8][kk + t    ];
                af[mt][2] = As[rb + g    ][kk + t + 4];
                af[mt][3] = As[rb + g + 8][kk + t + 4];
            }
#pragma unroll
            for (int nt = 0; nt < 4; nt++) {
                const int nb = warpBn + (nt << 3);
                bf[nt][0] = Bs[nb + g][kk + t    ];
                bf[nt][1] = Bs[nb + g][kk + t + 4];
            }
#pragma unroll
            for (int mt = 0; mt < 4; mt++)
#pragma unroll
                for (int nt = 0; nt < 4; nt++)
                    mma_tf32(acc[mt][nt][0], acc[mt][nt][1],
                             acc[mt][nt][2], acc[mt][nt][3],
                             af[mt][0], af[mt][1], af[mt][2], af[mt][3],
                             bf[nt][0], bf[nt][1]);
        }
    }

#pragma unroll
    for (int nt = 0; nt < 4; nt++) {
        const int n = n0 + warpBn + (nt << 3) + (t << 1);
        const float bx = bias[n], by = bias[n + 1];
#pragma unroll
        for (int mt = 0; mt < 4; mt++) {
            const int r0 = m0 + warpAm + (mt << 4) + g;
            const int r1 = r0 + 8;
            float2 v0 = make_float2(acc[mt][nt][0] + bx, acc[mt][nt][1] + by);
            float2 v1 = make_float2(acc[mt][nt][2] + bx, acc[mt][nt][3] + by);
            if (layout == 0) {
                *(float2*)(C + (size_t)r0 * DIMK + n) = v0;
                *(float2*)(C + (size_t)r1 * DIMK + n) = v1;
            } else {
                const int h_ = n >> 6, d_ = n & 63;
                const int b0_ = r0 >> 12, s0_ = r0 & 4095;
                const int b1_ = r1 >> 12, s1_ = r1 & 4095;
                *(float2*)(C + (((size_t)(b0_ * H + h_)) * SEQ + s0_) * HD + d_) = v0;
                *(float2*)(C + (((size_t)(b1_ * H + h_)) * SEQ + s1_) * HD + d_) = v1;
            }
        }
    }
}

// ---------------------------------------------------------------------------
// Tensorized sliding-window attention.
// CTA = (b, h, 64-query tile), 128 threads / 4 warps, warp owns 16 rows.
// Per 64-key tile: S = Q K^T (tf32 mma), base-2 online softmax, O += P V.
// ---------------------------------------------------------------------------
#define AST 68          // smem row stride (words): 4g+t banks conflict-free
#define SMEM_AMMA (4 * 64 * AST * 4)   // Qs,Ks,Vs,Ps = 69632 B

__global__ void __launch_bounds__(128) attn_mma()
{
    extern __shared__ __align__(16) uint32_t smu[];
    uint32_t* Qs = smu;                  // [64][AST] tf32
    uint32_t* Ks = smu + 64 * AST;       // [64][AST] tf32
    uint32_t* Vs = smu + 2 * 64 * AST;   // [64][AST] tf32
    uint32_t* Ps = smu + 3 * 64 * AST;   // [64][AST] tf32

    const int tid  = threadIdx.x;
    const int w    = tid >> 5;
    const int lane = tid & 31;
    const int g    = lane >> 2;
    const int t    = lane & 3;

    const int qi = blockIdx.x & 63;            // 64 query tiles
    const int h  = (blockIdx.x >> 6) & 15;
    const int b  = blockIdx.x >> 10;
    const int p0 = qi << 6;

    const size_t headoff = ((size_t)(b * H + h)) * SEQ * HD;
    const float* qbase = g_q + headoff;
    const float* kbase = g_k + headoff;
    const float* vbase = g_v + headoff;

    // stage Q (tf32): [64][64] -> Qs
#pragma unroll
    for (int it = 0; it < 8; it++) {
        const int u = tid + (it << 7);
        const int row = u >> 4, c4 = (u & 15) << 2;
        float4 v = *(const float4*)(qbase + (size_t)(p0 + row) * HD + c4);
        uint4 tv;
        tv.x = f32_tf32(v.x); tv.y = f32_tf32(v.y);
        tv.z = f32_tf32(v.z); tv.w = f32_tf32(v.w);
        *(uint4*)&Qs[row * AST + c4] = tv;
    }
    __syncthreads();

    const int r0 = (w << 4) + g;          // warp row base + group
    const int q0 = p0 + r0;
    const int q1 = q0 + 8;

    float O[8][4];
#pragma unroll
    for (int nt = 0; nt < 8; nt++)
#pragma unroll
        for (int r = 0; r < 4; r++) O[nt][r] = 0.f;
    float m0 = -1.0e4f, m1 = -1.0e4f, l0 = 0.f, l1 = 0.f;

    const float SC = 0.125f * 1.44269504f;   // hd^-0.5 * log2(e)

    const int ktlo = (qi >= 8) ? (qi - 8) : 0;
    for (int kt = ktlo; kt <= qi; kt++) {
        const int t0 = kt << 6;

        __syncthreads();   // prior iteration's Ks/Vs reads complete
#pragma unroll
        for (int it = 0; it < 8; it++) {
            const int u = tid + (it << 7);
            const int row = u >> 4, c4 = (u & 15) << 2;
            float4 kv = *(const float4*)(kbase + (size_t)(t0 + row) * HD + c4);
            float4 vv = *(const float4*)(vbase + (size_t)(t0 + row) * HD + c4);
            uint4 tk, tv;
            tk.x = f32_tf32(kv.x); tk.y = f32_tf32(kv.y);
            tk.z = f32_tf32(kv.z); tk.w = f32_tf32(kv.w);
            tv.x = f32_tf32(vv.x); tv.y = f32_tf32(vv.y);
            tv.z = f32_tf32(vv.z); tv.w = f32_tf32(vv.w);
            *(uint4*)&Ks[row * AST + c4] = tk;
            *(uint4*)&Vs[row * AST + c4] = tv;
        }
        __syncthreads();

        // S = Q K^T
        float s[8][4];
#pragma unroll
        for (int nt = 0; nt < 8; nt++)
#pragma unroll
            for (int r = 0; r < 4; r++) s[nt][r] = 0.f;

#pragma unroll
        for (int ks = 0; ks < 8; ks++) {
            const int kk = ks << 3;
            const uint32_t a0 = Qs[r0 * AST + kk + t];
            const uint32_t a1 = Qs[(r0 + 8) * AST + kk + t];
            const uint32_t a2 = Qs[r0 * AST + kk + t + 4];
            const uint32_t a3 = Qs[(r0 + 8) * AST + kk + t + 4];
#pragma unroll
            for (int nt = 0; nt < 8; nt++) {
                const uint32_t b0 = Ks[((nt << 3) + g) * AST + kk + t];
                const uint32_t b1 = Ks[((nt << 3) + g) * AST + kk + t + 4];
                mma_tf32(s[nt][0], s[nt][1], s[nt][2], s[nt][3],
                         a0, a1, a2, a3, b0, b1);
            }
        }

        // mask + scale (log2 domain)
        float rmax0 = -3.0e4f, rmax1 = -3.0e4f;
#pragma unroll
        for (int nt = 0; nt < 8; nt++) {
            const int c = t0 + (nt << 3) + (t << 1);
            s[nt][0] = ((unsigned)(q0 - c)     < 512u) ? s[nt][0] * SC : -3.0e4f;
            s[nt][1] = ((unsigned)(q0 - c - 1) < 512u) ? s[nt][1] * SC : -3.0e4f;
            s[nt][2] = ((unsigned)(q1 - c)     < 512u) ? s[nt][2] * SC : -3.0e4f;
            s[nt][3] = ((unsigned)(q1 - c - 1) < 512u) ? s[nt][3] * SC : -3.0e4f;
            rmax0 = fmaxf(rmax0, fmaxf(s[nt][0], s[nt][1]));
            rmax1 = fmaxf(rmax1, fmaxf(s[nt][2], s[nt][3]));
        }
        rmax0 = fmaxf(rmax0, __shfl_xor_sync(0xffffffffu, rmax0, 1));
        rmax0 = fmaxf(rmax0, __shfl_xor_sync(0xffffffffu, rmax0, 2));
        rmax1 = fmaxf(rmax1, __shfl_xor_sync(0xffffffffu, rmax1, 1));
        rmax1 = fmaxf(rmax1, __shfl_xor_sync(0xffffffffu, rmax1, 2));

        const float mn0 = fmaxf(m0, rmax0);
        const float mn1 = fmaxf(m1, rmax1);
        const float al0 = ex2f(m0 - mn0);
        const float al1 = ex2f(m1 - mn1);
        m0 = mn0; m1 = mn1;

        float rs0 = 0.f, rs1 = 0.f;
#pragma unroll
        for (int nt = 0; nt < 8; nt++) {
            const float p00 = ex2f(s[nt][0] - mn0);
            const float p01 = ex2f(s[nt][1] - mn0);
            const float p10 = ex2f(s[nt][2] - mn1);
            const float p11 = ex2f(s[nt][3] - mn1);
            rs0 += p00 + p01;
            rs1 += p10 + p11;
            const int cc = (nt << 3) + (t << 1);
            uint2 w0 = make_uint2(f32_tf32(p00), f32_tf32(p01));
            uint2 w1 = make_uint2(f32_tf32(p10), f32_tf32(p11));
            *(uint2*)&Ps[r0 * AST + cc]       = w0;
            *(uint2*)&Ps[(r0 + 8) * AST + cc] = w1;
        }
        rs0 += __shfl_xor_sync(0xffffffffu, rs0, 1);
        rs0 += __shfl_xor_sync(0xffffffffu, rs0, 2);
        rs1 += __shfl_xor_sync(0xffffffffu, rs1, 1);
        rs1 += __shfl_xor_sync(0xffffffffu, rs1, 2);

        l0 = l0 * al0 + rs0;
        l1 = l1 * al1 + rs1;
#pragma unroll
        for (int nt = 0; nt < 8; nt++) {
            O[nt][0] *= al0; O[nt][1] *= al0;
            O[nt][2] *= al1; O[nt][3] *= al1;
        }
        __syncwarp();   // Ps warp-private: writer == reader warp

        // O += P V   (B-frag reads V transposed from [t][d] tile)
#pragma unroll
        for (int ks = 0; ks < 8; ks++) {
            const int kk = ks << 3;
            const uint32_t a0 = Ps[r0 * AST + kk + t];
            const uint32_t a1 = Ps[(r0 + 8) * AST + kk + t];
            const uint32_t a2 = Ps[r0 * AST + kk + t + 4];
            const uint32_t a3 = Ps[(r0 + 8) * AST + kk + t + 4];
#pragma unroll
            for (int nt = 0; nt < 8; nt++) {
                const uint32_t b0 = Vs[(kk + t) * AST + (nt << 3) + g];
                const uint32_t b1 = Vs[(kk + t + 4) * AST + (nt << 3) + g];
                mma_tf32(O[nt][0], O[nt][1], O[nt][2], O[nt][3],
                         a0, a1, a2, a3, b0, b1);
            }
        }
    }

    // epilogue: normalize, write [B,S,D]
    const float inv0 = 1.f / l0;
    const float inv1 = 1.f / l1;
    float* dst0 = g_att + ((size_t)b * SEQ + q0) * DIMK + h * HD;
    float* dst1 = g_att + ((size_t)b * SEQ + q1) * DIMK + h * HD;
#pragma unroll
    for (int nt = 0; nt < 8; nt++) {
        const int cc = (nt << 3) + (t << 1);
        *(float2*)(dst0 + cc) = make_float2(O[nt][0] * inv0, O[nt][1] * inv0);
        *(float2*)(dst1 + cc) = make_float2(O[nt][2] * inv1, O[nt][3] * inv1);
    }
}

// ---------------------------------------------------------------------------
extern "C" void kernel_launch(void* const* d_in, const int* in_sizes, int n_in,
                              void* d_out, int out_size)
{
    const float* x  = (const float*)d_in[0];
    const float* Wq = (const float*)d_in[1];
    const float* bq = (const float*)d_in[2];
    const float* Wk = (const float*)d_in[3];
    const float* bk = (const float*)d_in[4];
    const float* Wv = (const float*)d_in[5];
    const float* bv = (const float*)d_in[6];
    const float* Wo = (const float*)d_in[7];
    const float* bo = (const float*)d_in[8];
    float* out = (float*)d_out;

    float *qp, *kp, *vp, *ap;
    cudaGetSymbolAddress((void**)&qp, g_q);
    cudaGetSymbolAddress((void**)&kp, g_k);
    cudaGetSymbolAddress((void**)&vp, g_v);
    cudaGetSymbolAddress((void**)&ap, g_att);

    cudaFuncSetAttribute(attn_mma,
                         cudaFuncAttributeMaxDynamicSharedMemorySize, SMEM_AMMA);

    dim3 gg(DIMK / BN, M_TOT / BM);   // (8, 64)
    gemm_mma<<<gg, 256>>>(x, Wq, bq, qp, 1);
    gemm_mma<<<gg, 256>>>(x, Wk, bk, kp, 1);
    gemm_mma<<<gg, 256>>>(x, Wv, bv, vp, 1);
    attn_mma<<<BSZ * H * (SEQ / 64), 128, SMEM_AMMA>>>();  // 2048 CTAs
    gemm_mma<<<gg, 256>>>(ap, Wo, bo, out, 0);
}